// round 2
// baseline (speedup 1.0000x reference)
#include <cuda_runtime.h>
#include <math.h>

// ---------------- problem constants ----------------
#define Bsz 16
#define Nn  1024
#define Cin 2
#define Tt  12
#define HIDc 64
#define T1  10          // T-2
#define T2n 8           // T-4
#define OC  384         // OUT*PRED
#define Ee  16384
#define BT1 (Bsz*T1)    // 160
#define K2  192         // HID*KT for conv2
#define STAT_CNT 49152.0f  // B*T2n*OC per-node BN count

typedef unsigned long long ull;

// ---------------- f32x2 packed-FMA helpers ----------------
__device__ __forceinline__ ull pack2(float x, float y) {
    ull r;
    asm("mov.b64 %0, {%1, %2};" : "=l"(r) : "f"(x), "f"(y));
    return r;
}
__device__ __forceinline__ float2 unpack2(ull v) {
    float2 r;
    asm("mov.b64 {%0, %1}, %2;" : "=f"(r.x), "=f"(r.y) : "l"(v));
    return r;
}
__device__ __forceinline__ ull ffma2(ull a, ull b, ull c) {
    ull d;
    asm("fma.rn.f32x2 %0, %1, %2, %3;" : "=l"(d) : "l"(a), "l"(b), "l"(c));
    return d;
}

// ---------------- device scratch (static, no allocs) ----------------
__device__ float g_T0 [Nn*BT1*HIDc];   // (n, b*10+t, h)
__device__ float g_Tx1[Nn*BT1*HIDc];
__device__ float g_Tx2[Nn*BT1*HIDc];
__device__ float g_Tg [Nn*BT1*HIDc];
__device__ float g_last[Bsz*Nn*OC];    // (b*Nn+n)*OC + o  (t''=7 slice, pre-BN)
__device__ float g_wt [3*K2*OC];       // transposed conv2 weights: [s][k][o]
__device__ float g_deg[Nn];
__device__ float g_dinv[Nn];
__device__ int   g_cntv[Nn];
__device__ int   g_indptr[Nn];
__device__ int   g_counter[Nn];
__device__ int   g_csr_row[Ee];
__device__ float g_csr_nrm[Ee];
__device__ float g_sum[Nn];
__device__ float g_sumsq[Nn];

// ---------------- init: zero per-launch state ----------------
__global__ void k_init() {
    int i = threadIdx.x;                 // 1024 threads, 1 block
    g_deg[i] = 0.f; g_cntv[i] = 0; g_counter[i] = 0;
    g_sum[i] = 0.f; g_sumsq[i] = 0.f;
}

// ---------------- degree + per-dest count ----------------
__global__ void k_deg(const int* __restrict__ ei, const float* __restrict__ ew) {
    int e = blockIdx.x * blockDim.x + threadIdx.x;
    if (e >= Ee) return;
    int r = ei[e], c = ei[Ee + e];
    if (r != c) atomicAdd(&g_deg[r], ew[e]);
    atomicAdd(&g_cntv[c], 1);
}

// ---------------- dinv + exclusive scan of counts ----------------
__global__ void k_scan() {
    __shared__ int s[Nn];
    int t = threadIdx.x;                 // 1024 threads
    float d = g_deg[t];
    g_dinv[t] = (d > 0.f) ? rsqrtf(d) : 0.f;
    int c = g_cntv[t];
    s[t] = c;
    __syncthreads();
    for (int off = 1; off < Nn; off <<= 1) {
        int v = (t >= off) ? s[t - off] : 0;
        __syncthreads();
        s[t] += v;
        __syncthreads();
    }
    g_indptr[t] = s[t] - c;              // exclusive prefix
}

// ---------------- scatter edges into CSR (by destination) ----------------
__global__ void k_scatter(const int* __restrict__ ei, const float* __restrict__ ew) {
    int e = blockIdx.x * blockDim.x + threadIdx.x;
    if (e >= Ee) return;
    int r = ei[e], c = ei[Ee + e];
    float nm = (r == c) ? 0.f : -(g_dinv[r] * ew[e] * g_dinv[c]);
    int pos = g_indptr[c] + atomicAdd(&g_counter[c], 1);
    g_csr_row[pos] = r;
    g_csr_nrm[pos] = nm;
}

// ---------------- temporal conv 1 (C=2 -> 64, gated GLU) ----------------
__global__ __launch_bounds__(64) void k_conv1(
    const float* __restrict__ X,
    const float* __restrict__ w1, const float* __restrict__ b1,
    const float* __restrict__ w2, const float* __restrict__ b2,
    const float* __restrict__ w3, const float* __restrict__ b3)
{
    int bid = blockIdx.x;
    int n = bid >> 4, b = bid & 15;
    int h = threadIdx.x;
    __shared__ float sx[2][12];
    if (h < 24) {
        int c = h / 12, t = h % 12;
        sx[c][t] = X[((b * Nn + n) * 2 + c) * 12 + t];
    }
    float w1r[6], w2r[6], w3r[6];
#pragma unroll
    for (int j = 0; j < 6; j++) {
        w1r[j] = w1[h * 6 + j];
        w2r[j] = w2[h * 6 + j];
        w3r[j] = w3[h * 6 + j];
    }
    float bb1 = b1[h], bb2 = b2[h], bb3 = b3[h];
    __syncthreads();
#pragma unroll
    for (int tp = 0; tp < T1; tp++) {
        float P = bb1, Q = bb2, R = bb3;
#pragma unroll
        for (int c = 0; c < 2; c++)
#pragma unroll
            for (int k = 0; k < 3; k++) {
                float v = sx[c][tp + k];
                P += v * w1r[c * 3 + k];
                Q += v * w2r[c * 3 + k];
                R += v * w3r[c * 3 + k];
            }
        float sg = 1.f / (1.f + expf(-Q));
        float val = P * sg + R;
        val = val > 0.f ? val : 0.f;
        g_T0[(n * BT1 + b * T1 + tp) * HIDc + h] = val;
    }
}

// ---------------- conv2 weight transpose: [s][k=(dt*64+h)][o] ----------------
__global__ void k_wtrans(const float* __restrict__ w1,
                         const float* __restrict__ w2,
                         const float* __restrict__ w3)
{
    int idx = blockIdx.x * blockDim.x + threadIdx.x;
    if (idx >= 3 * K2 * OC) return;
    int s = idx / (K2 * OC);
    int r = idx % (K2 * OC);
    int k = r / OC, o = r % OC;
    int h = k & 63, dt = k >> 6;
    const float* w = (s == 0) ? w1 : (s == 1) ? w2 : w3;
    g_wt[idx] = w[(o * HIDc + h) * 3 + dt];
}

// ---------------- graph propagation (gather CSR) ----------------
__global__ __launch_bounds__(256) void k_prop(int mode) {
    const float* __restrict__ z = (mode == 0) ? g_T0 : g_Tx1;
    float* __restrict__ out = (mode == 0) ? g_Tx1 : g_Tx2;
    int j = blockIdx.x;
    int tid = threadIdx.x;
    int hq = tid & 15;            // h = hq*4
    int g = tid >> 4;             // 16 groups, 10 bt each
    float4 acc[10];
#pragma unroll
    for (int i = 0; i < 10; i++) acc[i] = make_float4(0.f, 0.f, 0.f, 0.f);

    int start = g_indptr[j], cnt = g_cntv[j];
    __shared__ int sr[64];
    __shared__ float sn[64];
    for (int eb = 0; eb < cnt; eb += 64) {
        int m = cnt - eb; if (m > 64) m = 64;
        if (tid < m) { sr[tid] = g_csr_row[start + eb + tid]; sn[tid] = g_csr_nrm[start + eb + tid]; }
        __syncthreads();
        for (int e = 0; e < m; e++) {
            int r = sr[e];
            float nm = sn[e];
            const float4* zp = (const float4*)z + (size_t)(r * BT1 + g * 10) * 16 + hq;
#pragma unroll
            for (int i = 0; i < 10; i++) {
                float4 v = zp[(size_t)i * 16];
                acc[i].x += nm * v.x; acc[i].y += nm * v.y;
                acc[i].z += nm * v.z; acc[i].w += nm * v.w;
            }
        }
        __syncthreads();
    }
    float4* op = (float4*)out + (size_t)(j * BT1 + g * 10) * 16 + hq;
    if (mode == 0) {
#pragma unroll
        for (int i = 0; i < 10; i++) op[(size_t)i * 16] = acc[i];
    } else {
        const float4* sp = (const float4*)g_T0 + (size_t)(j * BT1 + g * 10) * 16 + hq;
#pragma unroll
        for (int i = 0; i < 10; i++) {
            float4 s0 = sp[(size_t)i * 16];
            float4 o4;
            o4.x = 2.f * acc[i].x - s0.x; o4.y = 2.f * acc[i].y - s0.y;
            o4.z = 2.f * acc[i].z - s0.z; o4.w = 2.f * acc[i].w - s0.w;
            op[(size_t)i * 16] = o4;
        }
    }
}

// ---------------- cheb combine (f32x2): Tg = relu(T0@W0 + Tx1@W1 + Tx2@W2 + b) ----------------
// grid 2560, 256 threads, 64x64 tile, K=3*64. Packed along m.
__global__ __launch_bounds__(256) void k_chebmm(const float* __restrict__ chebW,
                                               const float* __restrict__ chebB)
{
    __shared__ float As[16][66];                    // [kk][m], stride 66 (8B aligned rows)
    __shared__ __align__(16) float Bsd[16][128];    // [kk][2*f] duplicated (w,w)
    int m0 = blockIdx.x * 64;
    int tid = threadIdx.x;
    int tx = tid & 15, ty = tid >> 4;       // f = tx*4 .. +3 ; m pairs at m0+ty*4
    ull acc[2][4];
#pragma unroll
    for (int pi = 0; pi < 2; pi++)
#pragma unroll
        for (int i = 0; i < 4; i++) acc[pi][i] = 0ULL;

    const float* srcs[3] = { g_T0, g_Tx1, g_Tx2 };
    int lkk = tid & 15, lmi = tid >> 4;     // A loader
    int lo = tid & 63, lkq = tid >> 6;      // B loader (lo = f, lkq 0..3)

    for (int s = 0; s < 3; s++) {
        const float* A = srcs[s];
        const float* W = chebW + s * (HIDc * HIDc);
        for (int kc = 0; kc < 4; kc++) {
#pragma unroll
            for (int p = 0; p < 4; p++)
                As[lkk][lmi + 16 * p] = A[(size_t)(m0 + lmi + 16 * p) * HIDc + kc * 16 + lkk];
#pragma unroll
            for (int p = 0; p < 4; p++) {
                int kk = lkq * 4 + p;
                float w = W[(kc * 16 + kk) * HIDc + lo];
                *(ull*)&Bsd[kk][2 * lo] = pack2(w, w);
            }
            __syncthreads();
#pragma unroll
            for (int kk = 0; kk < 16; kk++) {
                const ull* ap = (const ull*)&As[kk][ty * 4];
                ull a0 = ap[0], a1 = ap[1];
                const ull* bp = (const ull*)&Bsd[kk][tx * 8];
                ull b0 = bp[0], b1 = bp[1], b2 = bp[2], b3 = bp[3];
                acc[0][0] = ffma2(a0, b0, acc[0][0]);
                acc[0][1] = ffma2(a0, b1, acc[0][1]);
                acc[0][2] = ffma2(a0, b2, acc[0][2]);
                acc[0][3] = ffma2(a0, b3, acc[0][3]);
                acc[1][0] = ffma2(a1, b0, acc[1][0]);
                acc[1][1] = ffma2(a1, b1, acc[1][1]);
                acc[1][2] = ffma2(a1, b2, acc[1][2]);
                acc[1][3] = ffma2(a1, b3, acc[1][3]);
            }
            __syncthreads();
        }
    }
    float bb[4];
#pragma unroll
    for (int jj = 0; jj < 4; jj++) bb[jj] = chebB[tx * 4 + jj];
#pragma unroll
    for (int pi = 0; pi < 2; pi++) {
        float2 c0 = unpack2(acc[pi][0]);
        float2 c1 = unpack2(acc[pi][1]);
        float2 c2 = unpack2(acc[pi][2]);
        float2 c3 = unpack2(acc[pi][3]);
        int m = m0 + ty * 4 + 2 * pi;
        float4 e4, o4;
        float v;
        v = c0.x + bb[0]; e4.x = v > 0.f ? v : 0.f;
        v = c1.x + bb[1]; e4.y = v > 0.f ? v : 0.f;
        v = c2.x + bb[2]; e4.z = v > 0.f ? v : 0.f;
        v = c3.x + bb[3]; e4.w = v > 0.f ? v : 0.f;
        v = c0.y + bb[0]; o4.x = v > 0.f ? v : 0.f;
        v = c1.y + bb[1]; o4.y = v > 0.f ? v : 0.f;
        v = c2.y + bb[2]; o4.z = v > 0.f ? v : 0.f;
        v = c3.y + bb[3]; o4.w = v > 0.f ? v : 0.f;
        *(float4*)&g_Tg[(size_t)m * HIDc + tx * 4] = e4;
        *(float4*)&g_Tg[(size_t)(m + 1) * HIDc + tx * 4] = o4;
    }
}

// ---------------- temporal conv 2 (f32x2, 64 -> 384, gated) + BN stats + last slice ----------------
// grid (12, 1024): o-tile x node. 128 threads, BM=128, BO=32, K=192, 3 weight sets.
// Packed along m: thread (tx 0..7, ty 0..15) owns m = ty*8 + j (j=0..7, 4 pairs), o = o0+tx*4..+3.
__global__ __launch_bounds__(128) void k_conv2(
    const float* __restrict__ b1, const float* __restrict__ b2, const float* __restrict__ b3)
{
    __shared__ float As[16][130];                    // [kk][m], stride 130 (8B aligned rows)
    __shared__ __align__(16) float Bsd[3][16][64];   // [s][kk][2*o_local] duplicated
    int n = blockIdx.y;
    int o0 = blockIdx.x * 32;
    int tid = threadIdx.x;
    int tx = tid & 7, ty = tid >> 3;

    ull accP[4][4], accQ[4][4], accR[4][4];
#pragma unroll
    for (int pi = 0; pi < 4; pi++)
#pragma unroll
        for (int i = 0; i < 4; i++) { accP[pi][i] = 0ULL; accQ[pi][i] = 0ULL; accR[pi][i] = 0ULL; }

    int lkk = tid & 15, lm = tid >> 4;            // A loader: m = lm + 8p
    int lo = tid & 31, lk = tid >> 5;             // B loader: kk = lk*4 + p

    for (int kc = 0; kc < 12; kc++) {
        int dt = kc >> 2;
        int hbase = (kc & 3) * 16;
#pragma unroll
        for (int p = 0; p < 16; p++) {
            int m = lm + 8 * p;
            int rowg = p * T1 + lm + dt;          // b = p, t'' = lm
            As[lkk][m] = g_Tg[(size_t)(n * BT1 + rowg) * HIDc + hbase + lkk];
        }
#pragma unroll
        for (int s = 0; s < 3; s++)
#pragma unroll
            for (int p = 0; p < 4; p++) {
                int kk = lk * 4 + p;
                float w = g_wt[(size_t)s * (K2 * OC) + (size_t)(dt * 64 + hbase + kk) * OC + o0 + lo];
                *(ull*)&Bsd[s][kk][2 * lo] = pack2(w, w);
            }
        __syncthreads();
#pragma unroll
        for (int kk = 0; kk < 16; kk++) {
            const ull* ap = (const ull*)&As[kk][ty * 8];
            ull a0 = ap[0], a1 = ap[1], a2 = ap[2], a3 = ap[3];
            {
                ulonglong2 vA = *(const ulonglong2*)&Bsd[0][kk][tx * 8];
                ulonglong2 vB = *(const ulonglong2*)&Bsd[0][kk][tx * 8 + 4];
                accP[0][0] = ffma2(a0, vA.x, accP[0][0]);
                accP[0][1] = ffma2(a0, vA.y, accP[0][1]);
                accP[0][2] = ffma2(a0, vB.x, accP[0][2]);
                accP[0][3] = ffma2(a0, vB.y, accP[0][3]);
                accP[1][0] = ffma2(a1, vA.x, accP[1][0]);
                accP[1][1] = ffma2(a1, vA.y, accP[1][1]);
                accP[1][2] = ffma2(a1, vB.x, accP[1][2]);
                accP[1][3] = ffma2(a1, vB.y, accP[1][3]);
                accP[2][0] = ffma2(a2, vA.x, accP[2][0]);
                accP[2][1] = ffma2(a2, vA.y, accP[2][1]);
                accP[2][2] = ffma2(a2, vB.x, accP[2][2]);
                accP[2][3] = ffma2(a2, vB.y, accP[2][3]);
                accP[3][0] = ffma2(a3, vA.x, accP[3][0]);
                accP[3][1] = ffma2(a3, vA.y, accP[3][1]);
                accP[3][2] = ffma2(a3, vB.x, accP[3][2]);
                accP[3][3] = ffma2(a3, vB.y, accP[3][3]);
            }
            {
                ulonglong2 vA = *(const ulonglong2*)&Bsd[1][kk][tx * 8];
                ulonglong2 vB = *(const ulonglong2*)&Bsd[1][kk][tx * 8 + 4];
                accQ[0][0] = ffma2(a0, vA.x, accQ[0][0]);
                accQ[0][1] = ffma2(a0, vA.y, accQ[0][1]);
                accQ[0][2] = ffma2(a0, vB.x, accQ[0][2]);
                accQ[0][3] = ffma2(a0, vB.y, accQ[0][3]);
                accQ[1][0] = ffma2(a1, vA.x, accQ[1][0]);
                accQ[1][1] = ffma2(a1, vA.y, accQ[1][1]);
                accQ[1][2] = ffma2(a1, vB.x, accQ[1][2]);
                accQ[1][3] = ffma2(a1, vB.y, accQ[1][3]);
                accQ[2][0] = ffma2(a2, vA.x, accQ[2][0]);
                accQ[2][1] = ffma2(a2, vA.y, accQ[2][1]);
                accQ[2][2] = ffma2(a2, vB.x, accQ[2][2]);
                accQ[2][3] = ffma2(a2, vB.y, accQ[2][3]);
                accQ[3][0] = ffma2(a3, vA.x, accQ[3][0]);
                accQ[3][1] = ffma2(a3, vA.y, accQ[3][1]);
                accQ[3][2] = ffma2(a3, vB.x, accQ[3][2]);
                accQ[3][3] = ffma2(a3, vB.y, accQ[3][3]);
            }
            {
                ulonglong2 vA = *(const ulonglong2*)&Bsd[2][kk][tx * 8];
                ulonglong2 vB = *(const ulonglong2*)&Bsd[2][kk][tx * 8 + 4];
                accR[0][0] = ffma2(a0, vA.x, accR[0][0]);
                accR[0][1] = ffma2(a0, vA.y, accR[0][1]);
                accR[0][2] = ffma2(a0, vB.x, accR[0][2]);
                accR[0][3] = ffma2(a0, vB.y, accR[0][3]);
                accR[1][0] = ffma2(a1, vA.x, accR[1][0]);
                accR[1][1] = ffma2(a1, vA.y, accR[1][1]);
                accR[1][2] = ffma2(a1, vB.x, accR[1][2]);
                accR[1][3] = ffma2(a1, vB.y, accR[1][3]);
                accR[2][0] = ffma2(a2, vA.x, accR[2][0]);
                accR[2][1] = ffma2(a2, vA.y, accR[2][1]);
                accR[2][2] = ffma2(a2, vB.x, accR[2][2]);
                accR[2][3] = ffma2(a2, vB.y, accR[2][3]);
                accR[3][0] = ffma2(a3, vA.x, accR[3][0]);
                accR[3][1] = ffma2(a3, vA.y, accR[3][1]);
                accR[3][2] = ffma2(a3, vB.x, accR[3][2]);
                accR[3][3] = ffma2(a3, vB.y, accR[3][3]);
            }
        }
        __syncthreads();
    }

    float bb1[4], bb2[4], bb3[4];
#pragma unroll
    for (int jj = 0; jj < 4; jj++) {
        bb1[jj] = b1[o0 + tx * 4 + jj];
        bb2[jj] = b2[o0 + tx * 4 + jj];
        bb3[jj] = b3[o0 + tx * 4 + jj];
    }
    float lsum = 0.f, lss = 0.f;
    float vlast[4];
#pragma unroll
    for (int pi = 0; pi < 4; pi++) {
#pragma unroll
        for (int i = 0; i < 4; i++) {
            float2 P = unpack2(accP[pi][i]);
            float2 Q = unpack2(accQ[pi][i]);
            float2 R = unpack2(accR[pi][i]);
            float qx = 1.f / (1.f + expf(-(Q.x + bb2[i])));
            float vx = (P.x + bb1[i]) * qx + (R.x + bb3[i]);
            vx = vx > 0.f ? vx : 0.f;
            float qy = 1.f / (1.f + expf(-(Q.y + bb2[i])));
            float vy = (P.y + bb1[i]) * qy + (R.y + bb3[i]);
            vy = vy > 0.f ? vy : 0.f;
            lsum += vx + vy;
            lss += vx * vx + vy * vy;
            if (pi == 3) vlast[i] = vy;      // t'' = 7
        }
    }
    // b index = ty; write last-timestep slice
    *(float4*)&g_last[(size_t)(ty * Nn + n) * OC + o0 + tx * 4] =
        make_float4(vlast[0], vlast[1], vlast[2], vlast[3]);

    // block reduce -> 2 atomics
    unsigned lane = tid & 31, warp = tid >> 5;
#pragma unroll
    for (int off = 16; off > 0; off >>= 1) {
        lsum += __shfl_down_sync(0xffffffffu, lsum, off);
        lss  += __shfl_down_sync(0xffffffffu, lss,  off);
    }
    __shared__ float wsum[4], wss[4];
    if (lane == 0) { wsum[warp] = lsum; wss[warp] = lss; }
    __syncthreads();
    if (tid == 0) {
        atomicAdd(&g_sum[n],   wsum[0] + wsum[1] + wsum[2] + wsum[3]);
        atomicAdd(&g_sumsq[n], wss[0] + wss[1] + wss[2] + wss[3]);
    }
}

// ---------------- final: BN + transpose to output ----------------
__global__ __launch_bounds__(384) void k_final(
    const float* __restrict__ gamma, const float* __restrict__ beta,
    float* __restrict__ out)
{
    int bid = blockIdx.x;
    int b = bid >> 10, n = bid & 1023;
    int c = threadIdx.x;
    float mean = g_sum[n] / STAT_CNT;
    float var = g_sumsq[n] / STAT_CNT - mean * mean;
    float inv = rsqrtf(var + 1e-5f);
    float ga = gamma[n], be = beta[n];
    float v = g_last[(size_t)bid * OC + c];
    out[(size_t)c * (Bsz * Nn) + b * Nn + n] = (v - mean) * inv * ga + be;
}

// ---------------- launch ----------------
extern "C" void kernel_launch(void* const* d_in, const int* in_sizes, int n_in,
                              void* d_out, int out_size)
{
    const float* X        = (const float*)d_in[0];
    const int*   ei       = (const int*)  d_in[1];
    const float* ew       = (const float*)d_in[2];
    const float* tc1_w1   = (const float*)d_in[3];
    const float* tc1_b1   = (const float*)d_in[4];
    const float* tc1_w2   = (const float*)d_in[5];
    const float* tc1_b2   = (const float*)d_in[6];
    const float* tc1_w3   = (const float*)d_in[7];
    const float* tc1_b3   = (const float*)d_in[8];
    const float* cheb_W   = (const float*)d_in[9];
    const float* cheb_b   = (const float*)d_in[10];
    const float* tc2_w1   = (const float*)d_in[11];
    const float* tc2_b1   = (const float*)d_in[12];
    const float* tc2_w2   = (const float*)d_in[13];
    const float* tc2_b2   = (const float*)d_in[14];
    const float* tc2_w3   = (const float*)d_in[15];
    const float* tc2_b3   = (const float*)d_in[16];
    const float* bn_gamma = (const float*)d_in[17];
    const float* bn_beta  = (const float*)d_in[18];
    float* out = (float*)d_out;

    k_init<<<1, 1024>>>();
    k_deg<<<Ee / 256, 256>>>(ei, ew);
    k_scan<<<1, 1024>>>();
    k_scatter<<<Ee / 256, 256>>>(ei, ew);
    k_conv1<<<Bsz * Nn, 64>>>(X, tc1_w1, tc1_b1, tc1_w2, tc1_b2, tc1_w3, tc1_b3);
    k_wtrans<<<(3 * K2 * OC + 255) / 256, 256>>>(tc2_w1, tc2_w2, tc2_w3);
    k_prop<<<Nn, 256>>>(0);
    k_prop<<<Nn, 256>>>(1);
    k_chebmm<<<(Nn * BT1) / 64, 256>>>(cheb_W, cheb_b);
    k_conv2<<<dim3(12, Nn), 128>>>(tc2_b1, tc2_b2, tc2_b3);
    k_final<<<Bsz * Nn, 384>>>(bn_gamma, bn_beta, out);
}

// round 4
// speedup vs baseline: 1.8438x; 1.8438x over previous
#include <cuda_runtime.h>
#include <math.h>
#include <stdint.h>

// ---------------- problem constants ----------------
#define Bsz 16
#define Nn  1024
#define Cin 2
#define Tt  12
#define HIDc 64
#define T1  10          // T-2
#define T2n 8           // T-4
#define OC  384         // OUT*PRED
#define Ee  16384
#define BT1 (Bsz*T1)    // 160
#define K2  192         // HID*KT for conv2
#define STAT_CNT 49152.0f  // B*T2n*OC per-node BN count

// ---------------- tf32 mma helpers ----------------
__device__ __forceinline__ uint32_t f2tf32(float f) {
    uint32_t u;
    asm("cvt.rna.tf32.f32 %0, %1;" : "=r"(u) : "f"(f));
    return u;
}
__device__ __forceinline__ void mma_tf32(float c[4], const uint32_t a[4],
                                         uint32_t b0, uint32_t b1) {
    asm volatile(
        "mma.sync.aligned.m16n8k8.row.col.f32.tf32.tf32.f32 "
        "{%0,%1,%2,%3},{%4,%5,%6,%7},{%8,%9},{%0,%1,%2,%3};"
        : "+f"(c[0]), "+f"(c[1]), "+f"(c[2]), "+f"(c[3])
        : "r"(a[0]), "r"(a[1]), "r"(a[2]), "r"(a[3]), "r"(b0), "r"(b1));
}

// ---------------- device scratch (static, no allocs) ----------------
__device__ float g_T0 [Nn*BT1*HIDc];   // (n, b*10+t, h)
__device__ float g_Tx1[Nn*BT1*HIDc];
__device__ float g_Tx2[Nn*BT1*HIDc];
__device__ float g_Tg [Nn*BT1*HIDc];
__device__ float g_last[Bsz*Nn*OC];    // (b*Nn+n)*OC + o  (t''=7 slice, pre-BN)
__device__ float g_wt [3*K2*OC];       // transposed conv2 weights: [s][k][o]
__device__ float g_deg[Nn];
__device__ float g_dinv[Nn];
__device__ int   g_cntv[Nn];
__device__ int   g_indptr[Nn];
__device__ int   g_counter[Nn];
__device__ int   g_csr_row[Ee];
__device__ float g_csr_nrm[Ee];
__device__ float g_sum[Nn];
__device__ float g_sumsq[Nn];

// ---------------- init ----------------
__global__ void k_init() {
    int i = threadIdx.x;
    g_deg[i] = 0.f; g_cntv[i] = 0; g_counter[i] = 0;
    g_sum[i] = 0.f; g_sumsq[i] = 0.f;
}

// ---------------- degree + per-dest count ----------------
__global__ void k_deg(const int* __restrict__ ei, const float* __restrict__ ew) {
    int e = blockIdx.x * blockDim.x + threadIdx.x;
    if (e >= Ee) return;
    int r = ei[e], c = ei[Ee + e];
    if (r != c) atomicAdd(&g_deg[r], ew[e]);
    atomicAdd(&g_cntv[c], 1);
}

// ---------------- dinv + exclusive scan ----------------
__global__ void k_scan() {
    __shared__ int s[Nn];
    int t = threadIdx.x;
    float d = g_deg[t];
    g_dinv[t] = (d > 0.f) ? rsqrtf(d) : 0.f;
    int c = g_cntv[t];
    s[t] = c;
    __syncthreads();
    for (int off = 1; off < Nn; off <<= 1) {
        int v = (t >= off) ? s[t - off] : 0;
        __syncthreads();
        s[t] += v;
        __syncthreads();
    }
    g_indptr[t] = s[t] - c;
}

// ---------------- scatter edges into CSR ----------------
__global__ void k_scatter(const int* __restrict__ ei, const float* __restrict__ ew) {
    int e = blockIdx.x * blockDim.x + threadIdx.x;
    if (e >= Ee) return;
    int r = ei[e], c = ei[Ee + e];
    float nm = (r == c) ? 0.f : -(g_dinv[r] * ew[e] * g_dinv[c]);
    int pos = g_indptr[c] + atomicAdd(&g_counter[c], 1);
    g_csr_row[pos] = r;
    g_csr_nrm[pos] = nm;
}

// ---------------- temporal conv 1 ----------------
__global__ __launch_bounds__(64) void k_conv1(
    const float* __restrict__ X,
    const float* __restrict__ w1, const float* __restrict__ b1,
    const float* __restrict__ w2, const float* __restrict__ b2,
    const float* __restrict__ w3, const float* __restrict__ b3)
{
    int bid = blockIdx.x;
    int n = bid >> 4, b = bid & 15;
    int h = threadIdx.x;
    __shared__ float sx[2][12];
    if (h < 24) {
        int c = h / 12, t = h % 12;
        sx[c][t] = X[((b * Nn + n) * 2 + c) * 12 + t];
    }
    float w1r[6], w2r[6], w3r[6];
#pragma unroll
    for (int j = 0; j < 6; j++) {
        w1r[j] = w1[h * 6 + j];
        w2r[j] = w2[h * 6 + j];
        w3r[j] = w3[h * 6 + j];
    }
    float bb1 = b1[h], bb2 = b2[h], bb3 = b3[h];
    __syncthreads();
#pragma unroll
    for (int tp = 0; tp < T1; tp++) {
        float P = bb1, Q = bb2, R = bb3;
#pragma unroll
        for (int c = 0; c < 2; c++)
#pragma unroll
            for (int k = 0; k < 3; k++) {
                float v = sx[c][tp + k];
                P += v * w1r[c * 3 + k];
                Q += v * w2r[c * 3 + k];
                R += v * w3r[c * 3 + k];
            }
        float sg = 1.f / (1.f + expf(-Q));
        float val = P * sg + R;
        val = val > 0.f ? val : 0.f;
        g_T0[(n * BT1 + b * T1 + tp) * HIDc + h] = val;
    }
}

// ---------------- conv2 weight transpose: [s][k=(dt*64+h)][o] ----------------
__global__ void k_wtrans(const float* __restrict__ w1,
                         const float* __restrict__ w2,
                         const float* __restrict__ w3)
{
    int idx = blockIdx.x * blockDim.x + threadIdx.x;
    if (idx >= 3 * K2 * OC) return;
    int s = idx / (K2 * OC);
    int r = idx % (K2 * OC);
    int k = r / OC, o = r % OC;
    int h = k & 63, dt = k >> 6;
    const float* w = (s == 0) ? w1 : (s == 1) ? w2 : w3;
    g_wt[idx] = w[(o * HIDc + h) * 3 + dt];
}

// ---------------- graph propagation (gather CSR) ----------------
__global__ __launch_bounds__(256) void k_prop(int mode) {
    const float* __restrict__ z = (mode == 0) ? g_T0 : g_Tx1;
    float* __restrict__ out = (mode == 0) ? g_Tx1 : g_Tx2;
    int j = blockIdx.x;
    int tid = threadIdx.x;
    int hq = tid & 15;
    int g = tid >> 4;
    float4 acc[10];
#pragma unroll
    for (int i = 0; i < 10; i++) acc[i] = make_float4(0.f, 0.f, 0.f, 0.f);

    int start = g_indptr[j], cnt = g_cntv[j];
    __shared__ int sr[64];
    __shared__ float sn[64];
    for (int eb = 0; eb < cnt; eb += 64) {
        int m = cnt - eb; if (m > 64) m = 64;
        if (tid < m) { sr[tid] = g_csr_row[start + eb + tid]; sn[tid] = g_csr_nrm[start + eb + tid]; }
        __syncthreads();
        for (int e = 0; e < m; e++) {
            int r = sr[e];
            float nm = sn[e];
            const float4* zp = (const float4*)z + (size_t)(r * BT1 + g * 10) * 16 + hq;
#pragma unroll
            for (int i = 0; i < 10; i++) {
                float4 v = zp[(size_t)i * 16];
                acc[i].x += nm * v.x; acc[i].y += nm * v.y;
                acc[i].z += nm * v.z; acc[i].w += nm * v.w;
            }
        }
        __syncthreads();
    }
    float4* op = (float4*)out + (size_t)(j * BT1 + g * 10) * 16 + hq;
    if (mode == 0) {
#pragma unroll
        for (int i = 0; i < 10; i++) op[(size_t)i * 16] = acc[i];
    } else {
        const float4* sp = (const float4*)g_T0 + (size_t)(j * BT1 + g * 10) * 16 + hq;
#pragma unroll
        for (int i = 0; i < 10; i++) {
            float4 s0 = sp[(size_t)i * 16];
            float4 o4;
            o4.x = 2.f * acc[i].x - s0.x; o4.y = 2.f * acc[i].y - s0.y;
            o4.z = 2.f * acc[i].z - s0.z; o4.w = 2.f * acc[i].w - s0.w;
            op[(size_t)i * 16] = o4;
        }
    }
}

// ---------------- cheb combine (scalar fp32) ----------------
__global__ __launch_bounds__(256) void k_chebmm(const float* __restrict__ chebW,
                                               const float* __restrict__ chebB)
{
    __shared__ float As[64][17];
    __shared__ __align__(16) float Bs[16][64];
    int m0 = blockIdx.x * 64;
    int tid = threadIdx.x;
    int tx = tid & 15, ty = tid >> 4;
    float acc[4][4];
#pragma unroll
    for (int i = 0; i < 4; i++)
#pragma unroll
        for (int jj = 0; jj < 4; jj++) acc[i][jj] = 0.f;

    const float* srcs[3] = { g_T0, g_Tx1, g_Tx2 };
    int lkk = tid & 15, lmi = tid >> 4;
    int lo = tid & 63, lkq = tid >> 6;

    for (int s = 0; s < 3; s++) {
        const float* A = srcs[s];
        const float* W = chebW + s * (HIDc * HIDc);
        for (int kc = 0; kc < 4; kc++) {
#pragma unroll
            for (int p = 0; p < 4; p++)
                As[lmi + 16 * p][lkk] = A[(size_t)(m0 + lmi + 16 * p) * HIDc + kc * 16 + lkk];
#pragma unroll
            for (int p = 0; p < 4; p++)
                Bs[lkq + 4 * p][lo] = W[(kc * 16 + lkq + 4 * p) * HIDc + lo];
            __syncthreads();
#pragma unroll
            for (int kk = 0; kk < 16; kk++) {
                float a[4];
#pragma unroll
                for (int i = 0; i < 4; i++) a[i] = As[ty * 4 + i][kk];
                float4 bv = *(const float4*)&Bs[kk][tx * 4];
#pragma unroll
                for (int i = 0; i < 4; i++) {
                    acc[i][0] += a[i] * bv.x; acc[i][1] += a[i] * bv.y;
                    acc[i][2] += a[i] * bv.z; acc[i][3] += a[i] * bv.w;
                }
            }
            __syncthreads();
        }
    }
    float bb[4];
#pragma unroll
    for (int jj = 0; jj < 4; jj++) bb[jj] = chebB[tx * 4 + jj];
#pragma unroll
    for (int i = 0; i < 4; i++) {
        int m = m0 + ty * 4 + i;
        float4 o4;
        float v0 = acc[i][0] + bb[0]; o4.x = v0 > 0.f ? v0 : 0.f;
        float v1 = acc[i][1] + bb[1]; o4.y = v1 > 0.f ? v1 : 0.f;
        float v2 = acc[i][2] + bb[2]; o4.z = v2 > 0.f ? v2 : 0.f;
        float v3 = acc[i][3] + bb[3]; o4.w = v3 > 0.f ? v3 : 0.f;
        *(float4*)&g_Tg[(size_t)m * HIDc + tx * 4] = o4;
    }
}

// ---------------- temporal conv 2: tf32 tensor-core mma ----------------
// grid (12, 1024): (o-tile of 32) x node. 128 threads = 4 warps.
// Per node: M = 128 (b*8 + t''), K = 192 (dt*64+h), N = 32 x 3 weight sets.
// Warp w owns m in [w*32, w*32+32): 2 m-tiles of 16. mma m16n8k8 tf32.
__global__ __launch_bounds__(128) void k_conv2(
    const float* __restrict__ b1, const float* __restrict__ b2, const float* __restrict__ b3)
{
    __shared__ uint32_t As2[128 * 10];       // [m][c*2 + half], c=k%4, half=k/4
    __shared__ uint32_t Bs2[3 * 4 * 32 * 2]; // [s][k%4][n][k/4]
    int n = blockIdx.y;
    int o0 = blockIdx.x * 32;
    int tid = threadIdx.x;
    int lane = tid & 31, w = tid >> 5;

    float acc[3][2][4][4];
#pragma unroll
    for (int s = 0; s < 3; s++)
#pragma unroll
        for (int mt = 0; mt < 2; mt++)
#pragma unroll
            for (int nt = 0; nt < 4; nt++)
#pragma unroll
                for (int i = 0; i < 4; i++) acc[s][mt][nt][i] = 0.f;

    int arow_b = tid >> 3, arow_t = tid & 7;  // b, t'' for A loader (m = tid)

    for (int kc = 0; kc < 24; kc++) {
        int dt = kc >> 3;
        int hbase = (kc & 7) * 8;
        // ---- load A chunk (128 x 8) as tf32: each thread loads its full row ----
        {
            const float* src = &g_Tg[((size_t)n * BT1 + arow_b * T1 + arow_t + dt) * HIDc + hbase];
            float4 av0 = *(const float4*)src;
            float4 av1 = *(const float4*)(src + 4);
            As2[tid * 10 + 0] = f2tf32(av0.x);
            As2[tid * 10 + 2] = f2tf32(av0.y);
            As2[tid * 10 + 4] = f2tf32(av0.z);
            As2[tid * 10 + 6] = f2tf32(av0.w);
            As2[tid * 10 + 1] = f2tf32(av1.x);
            As2[tid * 10 + 3] = f2tf32(av1.y);
            As2[tid * 10 + 5] = f2tf32(av1.z);
            As2[tid * 10 + 7] = f2tf32(av1.w);
        }
        // ---- load B chunk (3 sets x 8 x 32) as tf32 ----
#pragma unroll
        for (int q = 0; q < 6; q++) {
            int idx = tid + q * 128;        // 0..767
            int s = idx >> 8;
            int rem = idx & 255;
            int k = rem >> 5, nn = rem & 31;
            float wv = g_wt[(size_t)s * (K2 * OC) + (size_t)(dt * 64 + hbase + k) * OC + o0 + nn];
            Bs2[((s * 4 + (k & 3)) * 32 + nn) * 2 + (k >> 2)] = f2tf32(wv);
        }
        __syncthreads();
        // ---- fragments + mma ----
        int row = lane >> 2, c = lane & 3;
        uint32_t a[2][4];
#pragma unroll
        for (int mt = 0; mt < 2; mt++) {
            int base = (w * 32 + mt * 16 + row) * 10 + c * 2;
            uint2 t0 = *(const uint2*)&As2[base];        // {A[row][c], A[row][c+4]}
            uint2 t1 = *(const uint2*)&As2[base + 80];   // row+8
            a[mt][0] = t0.x; a[mt][1] = t1.x; a[mt][2] = t0.y; a[mt][3] = t1.y;
        }
#pragma unroll
        for (int s = 0; s < 3; s++)
#pragma unroll
            for (int nt = 0; nt < 4; nt++) {
                uint2 bv = *(const uint2*)&Bs2[((s * 4 + c) * 32 + nt * 8 + row) * 2];
                mma_tf32(acc[s][0][nt], a[0], bv.x, bv.y);
                mma_tf32(acc[s][1][nt], a[1], bv.x, bv.y);
            }
        __syncthreads();
    }

    // ---- epilogue: gate + relu + BN stats + last-timestep slice ----
    int row = lane >> 2, col2 = 2 * (lane & 3);
    float lsum = 0.f, lss = 0.f;
#pragma unroll
    for (int nt = 0; nt < 4; nt++) {
#pragma unroll
        for (int cc = 0; cc < 2; cc++) {
            int o = o0 + nt * 8 + col2 + cc;
            float bias1 = b1[o], bias2 = b2[o], bias3 = b3[o];
#pragma unroll
            for (int mt = 0; mt < 2; mt++) {
#pragma unroll
                for (int rh = 0; rh < 2; rh++) {
                    int m = w * 32 + mt * 16 + row + rh * 8;
                    float P = acc[0][mt][nt][rh * 2 + cc] + bias1;
                    float Q = acc[1][mt][nt][rh * 2 + cc] + bias2;
                    float R = acc[2][mt][nt][rh * 2 + cc] + bias3;
                    float sg = 1.f / (1.f + expf(-Q));
                    float v = P * sg + R;
                    v = v > 0.f ? v : 0.f;
                    lsum += v;
                    lss += v * v;
                    if ((m & 7) == 7) {
                        g_last[(size_t)((m >> 3) * Nn + n) * OC + o] = v;
                    }
                }
            }
        }
    }

    // block reduce -> 2 atomics
    unsigned ln = tid & 31, warp = tid >> 5;
#pragma unroll
    for (int off = 16; off > 0; off >>= 1) {
        lsum += __shfl_down_sync(0xffffffffu, lsum, off);
        lss  += __shfl_down_sync(0xffffffffu, lss,  off);
    }
    __shared__ float wsum[4], wss[4];
    if (ln == 0) { wsum[warp] = lsum; wss[warp] = lss; }
    __syncthreads();
    if (tid == 0) {
        atomicAdd(&g_sum[n],   wsum[0] + wsum[1] + wsum[2] + wsum[3]);
        atomicAdd(&g_sumsq[n], wss[0] + wss[1] + wss[2] + wss[3]);
    }
}

// ---------------- final: BN + transpose to output ----------------
__global__ __launch_bounds__(384) void k_final(
    const float* __restrict__ gamma, const float* __restrict__ beta,
    float* __restrict__ out)
{
    int bid = blockIdx.x;
    int b = bid >> 10, n = bid & 1023;
    int c = threadIdx.x;
    float mean = g_sum[n] / STAT_CNT;
    float var = g_sumsq[n] / STAT_CNT - mean * mean;
    float inv = rsqrtf(var + 1e-5f);
    float ga = gamma[n], be = beta[n];
    float v = g_last[(size_t)bid * OC + c];
    out[(size_t)c * (Bsz * Nn) + b * Nn + n] = (v - mean) * inv * ga + be;
}

// ---------------- launch ----------------
extern "C" void kernel_launch(void* const* d_in, const int* in_sizes, int n_in,
                              void* d_out, int out_size)
{
    const float* X        = (const float*)d_in[0];
    const int*   ei       = (const int*)  d_in[1];
    const float* ew       = (const float*)d_in[2];
    const float* tc1_w1   = (const float*)d_in[3];
    const float* tc1_b1   = (const float*)d_in[4];
    const float* tc1_w2   = (const float*)d_in[5];
    const float* tc1_b2   = (const float*)d_in[6];
    const float* tc1_w3   = (const float*)d_in[7];
    const float* tc1_b3   = (const float*)d_in[8];
    const float* cheb_W   = (const float*)d_in[9];
    const float* cheb_b   = (const float*)d_in[10];
    const float* tc2_w1   = (const float*)d_in[11];
    const float* tc2_b1   = (const float*)d_in[12];
    const float* tc2_w2   = (const float*)d_in[13];
    const float* tc2_b2   = (const float*)d_in[14];
    const float* tc2_w3   = (const float*)d_in[15];
    const float* tc2_b3   = (const float*)d_in[16];
    const float* bn_gamma = (const float*)d_in[17];
    const float* bn_beta  = (const float*)d_in[18];
    float* out = (float*)d_out;

    k_init<<<1, 1024>>>();
    k_deg<<<Ee / 256, 256>>>(ei, ew);
    k_scan<<<1, 1024>>>();
    k_scatter<<<Ee / 256, 256>>>(ei, ew);
    k_conv1<<<Bsz * Nn, 64>>>(X, tc1_w1, tc1_b1, tc1_w2, tc1_b2, tc1_w3, tc1_b3);
    k_wtrans<<<(3 * K2 * OC + 255) / 256, 256>>>(tc2_w1, tc2_w2, tc2_w3);
    k_prop<<<Nn, 256>>>(0);
    k_prop<<<Nn, 256>>>(1);
    k_chebmm<<<(Nn * BT1) / 64, 256>>>(cheb_W, cheb_b);
    k_conv2<<<dim3(12, Nn), 128>>>(tc2_b1, tc2_b2, tc2_b3);
    k_final<<<Bsz * Nn, 384>>>(bn_gamma, bn_beta, out);
}

// round 5
// speedup vs baseline: 2.5115x; 1.3621x over previous
#include <cuda_runtime.h>
#include <math.h>
#include <stdint.h>

// ---------------- problem constants ----------------
#define Bsz 16
#define Nn  1024
#define Cin 2
#define Tt  12
#define HIDc 64
#define T1  10          // T-2
#define T2n 8           // T-4
#define OC  384         // OUT*PRED
#define Ee  16384
#define BT1 (Bsz*T1)    // 160
#define K2  192         // HID*KT for conv2
#define STAT_CNT 49152.0f  // B*T2n*OC per-node BN count

// conv2 smem geometry
#define A_STRIDE 68                    // 64 + 4 pad -> conflict-free a-frag LDS
#define A_WORDS  (BT1 * A_STRIDE)      // 10880 u32
#define B_C_STRIDE 136                 // 128 + 8 pad -> conflict-free b-frag LDS.64
#define B_WORDS  (12 * B_C_STRIDE)     // 1632 u32 per buffer (3 sets x 4 c-phases)
#define CONV2_SMEM ((A_WORDS + 2 * B_WORDS) * 4)   // 56576 bytes

// ---------------- tf32 mma helpers ----------------
__device__ __forceinline__ uint32_t f2tf32(float f) {
    uint32_t u;
    asm("cvt.rna.tf32.f32 %0, %1;" : "=r"(u) : "f"(f));
    return u;
}
__device__ __forceinline__ void mma_tf32(float c[4], const uint32_t a[4],
                                         uint32_t b0, uint32_t b1) {
    asm volatile(
        "mma.sync.aligned.m16n8k8.row.col.f32.tf32.tf32.f32 "
        "{%0,%1,%2,%3},{%4,%5,%6,%7},{%8,%9},{%0,%1,%2,%3};"
        : "+f"(c[0]), "+f"(c[1]), "+f"(c[2]), "+f"(c[3])
        : "r"(a[0]), "r"(a[1]), "r"(a[2]), "r"(a[3]), "r"(b0), "r"(b1));
}

// ---------------- device scratch (static, no allocs) ----------------
__device__ float g_T0 [Nn*BT1*HIDc];   // (n, b*10+t, h)
__device__ float g_Tx1[Nn*BT1*HIDc];
__device__ float g_Tx2[Nn*BT1*HIDc];
__device__ float g_Tg [Nn*BT1*HIDc];   // tf32-rounded floats
__device__ float g_last[Bsz*Nn*OC];    // (b*Nn+n)*OC + o  (t''=7 slice, pre-BN)
__device__ uint32_t g_wt2[24*3*4*OC*2]; // conv2 weights tf32, [kc][s][c][o][half]
__device__ float g_deg[Nn];
__device__ float g_dinv[Nn];
__device__ int   g_cntv[Nn];
__device__ int   g_indptr[Nn];
__device__ int   g_counter[Nn];
__device__ int   g_csr_row[Ee];
__device__ float g_csr_nrm[Ee];
__device__ float g_sum[Nn];
__device__ float g_sumsq[Nn];

// ---------------- init ----------------
__global__ void k_init() {
    int i = threadIdx.x;
    g_deg[i] = 0.f; g_cntv[i] = 0; g_counter[i] = 0;
    g_sum[i] = 0.f; g_sumsq[i] = 0.f;
}

// ---------------- degree + per-dest count ----------------
__global__ void k_deg(const int* __restrict__ ei, const float* __restrict__ ew) {
    int e = blockIdx.x * blockDim.x + threadIdx.x;
    if (e >= Ee) return;
    int r = ei[e], c = ei[Ee + e];
    if (r != c) atomicAdd(&g_deg[r], ew[e]);
    atomicAdd(&g_cntv[c], 1);
}

// ---------------- dinv + exclusive scan ----------------
__global__ void k_scan() {
    __shared__ int s[Nn];
    int t = threadIdx.x;
    float d = g_deg[t];
    g_dinv[t] = (d > 0.f) ? rsqrtf(d) : 0.f;
    int c = g_cntv[t];
    s[t] = c;
    __syncthreads();
    for (int off = 1; off < Nn; off <<= 1) {
        int v = (t >= off) ? s[t - off] : 0;
        __syncthreads();
        s[t] += v;
        __syncthreads();
    }
    g_indptr[t] = s[t] - c;
}

// ---------------- scatter edges into CSR ----------------
__global__ void k_scatter(const int* __restrict__ ei, const float* __restrict__ ew) {
    int e = blockIdx.x * blockDim.x + threadIdx.x;
    if (e >= Ee) return;
    int r = ei[e], c = ei[Ee + e];
    float nm = (r == c) ? 0.f : -(g_dinv[r] * ew[e] * g_dinv[c]);
    int pos = g_indptr[c] + atomicAdd(&g_counter[c], 1);
    g_csr_row[pos] = r;
    g_csr_nrm[pos] = nm;
}

// ---------------- temporal conv 1 ----------------
__global__ __launch_bounds__(64) void k_conv1(
    const float* __restrict__ X,
    const float* __restrict__ w1, const float* __restrict__ b1,
    const float* __restrict__ w2, const float* __restrict__ b2,
    const float* __restrict__ w3, const float* __restrict__ b3)
{
    int bid = blockIdx.x;
    int n = bid >> 4, b = bid & 15;
    int h = threadIdx.x;
    __shared__ float sx[2][12];
    if (h < 24) {
        int c = h / 12, t = h % 12;
        sx[c][t] = X[((b * Nn + n) * 2 + c) * 12 + t];
    }
    float w1r[6], w2r[6], w3r[6];
#pragma unroll
    for (int j = 0; j < 6; j++) {
        w1r[j] = w1[h * 6 + j];
        w2r[j] = w2[h * 6 + j];
        w3r[j] = w3[h * 6 + j];
    }
    float bb1 = b1[h], bb2 = b2[h], bb3 = b3[h];
    __syncthreads();
#pragma unroll
    for (int tp = 0; tp < T1; tp++) {
        float P = bb1, Q = bb2, R = bb3;
#pragma unroll
        for (int c = 0; c < 2; c++)
#pragma unroll
            for (int k = 0; k < 3; k++) {
                float v = sx[c][tp + k];
                P += v * w1r[c * 3 + k];
                Q += v * w2r[c * 3 + k];
                R += v * w3r[c * 3 + k];
            }
        float sg = 1.f / (1.f + expf(-Q));
        float val = P * sg + R;
        val = val > 0.f ? val : 0.f;
        g_T0[(n * BT1 + b * T1 + tp) * HIDc + h] = val;
    }
}

// ---------------- conv2 weight prep: tf32 + fragment-layout swizzle ----------------
// dst [kc][s][c][o][half]; kc = dt*8 + h/8, c = (h%8)&3, half = (h%8)>>2
__global__ void k_wtrans(const float* __restrict__ w1,
                         const float* __restrict__ w2,
                         const float* __restrict__ w3)
{
    int idx = blockIdx.x * blockDim.x + threadIdx.x;
    if (idx >= 3 * K2 * OC) return;
    int s = idx / (K2 * OC);
    int r = idx % (K2 * OC);
    int k = r / OC, o = r % OC;
    int h = k & 63, dt = k >> 6;
    const float* w = (s == 0) ? w1 : (s == 1) ? w2 : w3;
    int kc = dt * 8 + (h >> 3);
    int kl = h & 7;
    int c = kl & 3, half = kl >> 2;
    g_wt2[(((kc * 3 + s) * 4 + c) * OC + o) * 2 + half] =
        f2tf32(w[(o * HIDc + h) * 3 + dt]);
}

// ---------------- graph propagation (gather CSR) ----------------
__global__ __launch_bounds__(256) void k_prop(int mode) {
    const float* __restrict__ z = (mode == 0) ? g_T0 : g_Tx1;
    float* __restrict__ out = (mode == 0) ? g_Tx1 : g_Tx2;
    int j = blockIdx.x;
    int tid = threadIdx.x;
    int hq = tid & 15;
    int g = tid >> 4;
    float4 acc[10];
#pragma unroll
    for (int i = 0; i < 10; i++) acc[i] = make_float4(0.f, 0.f, 0.f, 0.f);

    int start = g_indptr[j], cnt = g_cntv[j];
    __shared__ int sr[64];
    __shared__ float sn[64];
    for (int eb = 0; eb < cnt; eb += 64) {
        int m = cnt - eb; if (m > 64) m = 64;
        if (tid < m) { sr[tid] = g_csr_row[start + eb + tid]; sn[tid] = g_csr_nrm[start + eb + tid]; }
        __syncthreads();
        for (int e = 0; e < m; e++) {
            int r = sr[e];
            float nm = sn[e];
            const float4* zp = (const float4*)z + (size_t)(r * BT1 + g * 10) * 16 + hq;
#pragma unroll
            for (int i = 0; i < 10; i++) {
                float4 v = zp[(size_t)i * 16];
                acc[i].x += nm * v.x; acc[i].y += nm * v.y;
                acc[i].z += nm * v.z; acc[i].w += nm * v.w;
            }
        }
        __syncthreads();
    }
    float4* op = (float4*)out + (size_t)(j * BT1 + g * 10) * 16 + hq;
    if (mode == 0) {
#pragma unroll
        for (int i = 0; i < 10; i++) op[(size_t)i * 16] = acc[i];
    } else {
        const float4* sp = (const float4*)g_T0 + (size_t)(j * BT1 + g * 10) * 16 + hq;
#pragma unroll
        for (int i = 0; i < 10; i++) {
            float4 s0 = sp[(size_t)i * 16];
            float4 o4;
            o4.x = 2.f * acc[i].x - s0.x; o4.y = 2.f * acc[i].y - s0.y;
            o4.z = 2.f * acc[i].z - s0.z; o4.w = 2.f * acc[i].w - s0.w;
            op[(size_t)i * 16] = o4;
        }
    }
}

// ---------------- cheb combine (scalar fp32), stores Tg tf32-rounded ----------------
__global__ __launch_bounds__(256) void k_chebmm(const float* __restrict__ chebW,
                                               const float* __restrict__ chebB)
{
    __shared__ float As[64][17];
    __shared__ __align__(16) float Bs[16][64];
    int m0 = blockIdx.x * 64;
    int tid = threadIdx.x;
    int tx = tid & 15, ty = tid >> 4;
    float acc[4][4];
#pragma unroll
    for (int i = 0; i < 4; i++)
#pragma unroll
        for (int jj = 0; jj < 4; jj++) acc[i][jj] = 0.f;

    const float* srcs[3] = { g_T0, g_Tx1, g_Tx2 };
    int lkk = tid & 15, lmi = tid >> 4;
    int lo = tid & 63, lkq = tid >> 6;

    for (int s = 0; s < 3; s++) {
        const float* A = srcs[s];
        const float* W = chebW + s * (HIDc * HIDc);
        for (int kc = 0; kc < 4; kc++) {
#pragma unroll
            for (int p = 0; p < 4; p++)
                As[lmi + 16 * p][lkk] = A[(size_t)(m0 + lmi + 16 * p) * HIDc + kc * 16 + lkk];
#pragma unroll
            for (int p = 0; p < 4; p++)
                Bs[lkq + 4 * p][lo] = W[(kc * 16 + lkq + 4 * p) * HIDc + lo];
            __syncthreads();
#pragma unroll
            for (int kk = 0; kk < 16; kk++) {
                float a[4];
#pragma unroll
                for (int i = 0; i < 4; i++) a[i] = As[ty * 4 + i][kk];
                float4 bv = *(const float4*)&Bs[kk][tx * 4];
#pragma unroll
                for (int i = 0; i < 4; i++) {
                    acc[i][0] += a[i] * bv.x; acc[i][1] += a[i] * bv.y;
                    acc[i][2] += a[i] * bv.z; acc[i][3] += a[i] * bv.w;
                }
            }
            __syncthreads();
        }
    }
    float bb[4];
#pragma unroll
    for (int jj = 0; jj < 4; jj++) bb[jj] = chebB[tx * 4 + jj];
#pragma unroll
    for (int i = 0; i < 4; i++) {
        int m = m0 + ty * 4 + i;
        float4 o4;
        float v0 = acc[i][0] + bb[0]; v0 = v0 > 0.f ? v0 : 0.f;
        float v1 = acc[i][1] + bb[1]; v1 = v1 > 0.f ? v1 : 0.f;
        float v2 = acc[i][2] + bb[2]; v2 = v2 > 0.f ? v2 : 0.f;
        float v3 = acc[i][3] + bb[3]; v3 = v3 > 0.f ? v3 : 0.f;
        // store tf32-rounded so conv2 needs no cvt
        o4.x = __uint_as_float(f2tf32(v0));
        o4.y = __uint_as_float(f2tf32(v1));
        o4.z = __uint_as_float(f2tf32(v2));
        o4.w = __uint_as_float(f2tf32(v3));
        *(float4*)&g_Tg[(size_t)m * HIDc + tx * 4] = o4;
    }
}

// ---------------- temporal conv 2: tf32 mma, A resident in smem ----------------
// grid (6, 1024): (o-tile of 64) x node. 256 threads = 8 warps.
// Warp w owns m in [w*16, w*16+16) (one m16 tile). N = 64 -> 8 n8 tiles x 3 sets.
__global__ __launch_bounds__(256) void k_conv2(
    const float* __restrict__ b1, const float* __restrict__ b2, const float* __restrict__ b3)
{
    extern __shared__ uint32_t sh[];
    uint32_t* sA = sh;                 // [bt:160][h:64] stride A_STRIDE
    uint32_t* sB = sh + A_WORDS;       // 2 buffers of B_WORDS
    int n = blockIdx.y;
    int o0 = blockIdx.x * 64;
    int tid = threadIdx.x;
    int lane = tid & 31, w = tid >> 5;
    int r = lane >> 2, c = lane & 3;

    // ---- load full node A slice (tf32-rounded already) ----
    const uint4* gT = (const uint4*)(g_Tg + (size_t)n * (BT1 * HIDc));
#pragma unroll
    for (int q = 0; q < 10; q++) {
        int idx4 = tid + q * 256;          // 0..2559
        int bt = idx4 >> 4;
        int h4 = (idx4 & 15) * 4;
        *(uint4*)&sA[bt * A_STRIDE + h4] = gT[idx4];
    }
    // ---- preload B chunk 0 ----
    const uint2* gW = (const uint2*)g_wt2;
#pragma unroll
    for (int q = 0; q < 3; q++) {
        int idx2 = tid + q * 256;          // 0..767
        int sc = idx2 >> 6, j2 = idx2 & 63;
        *(uint2*)&sB[sc * B_C_STRIDE + j2 * 2] = gW[sc * 384 + o0 + j2];
    }
    __syncthreads();

    float acc[3][8][4];
#pragma unroll
    for (int s = 0; s < 3; s++)
#pragma unroll
        for (int nt = 0; nt < 8; nt++)
#pragma unroll
            for (int i = 0; i < 4; i++) acc[s][nt][i] = 0.f;

    for (int kc = 0; kc < 24; kc++) {
        int cur = (kc & 1) ? B_WORDS : 0;
        if (kc < 23) {
            int nxt = B_WORDS - cur;
            int gbase = (kc + 1) * 4608;
#pragma unroll
            for (int q = 0; q < 3; q++) {
                int idx2 = tid + q * 256;
                int sc = idx2 >> 6, j2 = idx2 & 63;
                *(uint2*)&sB[nxt + sc * B_C_STRIDE + j2 * 2] = gW[gbase + sc * 384 + o0 + j2];
            }
        }
        int dt = kc >> 3;
        int hbase = (kc & 7) << 3;
        int bt0 = 20 * w + r + dt;
        uint32_t a[4];
        a[0] = sA[bt0 * A_STRIDE + hbase + c];
        a[1] = sA[(bt0 + 10) * A_STRIDE + hbase + c];
        a[2] = sA[bt0 * A_STRIDE + hbase + c + 4];
        a[3] = sA[(bt0 + 10) * A_STRIDE + hbase + c + 4];
#pragma unroll
        for (int s = 0; s < 3; s++)
#pragma unroll
            for (int nt = 0; nt < 8; nt++) {
                uint2 bv = *(const uint2*)&sB[cur + (s * 4 + c) * B_C_STRIDE + (nt * 8 + r) * 2];
                mma_tf32(acc[s][nt], a, bv.x, bv.y);
            }
        __syncthreads();
    }

    // ---- epilogue: gate + relu + BN stats + last-timestep slice ----
    int col2 = c * 2;
    float lsum = 0.f, lss = 0.f;
#pragma unroll
    for (int nt = 0; nt < 8; nt++) {
#pragma unroll
        for (int cc = 0; cc < 2; cc++) {
            int o = o0 + nt * 8 + col2 + cc;
            float bias1 = b1[o], bias2 = b2[o], bias3 = b3[o];
#pragma unroll
            for (int rh = 0; rh < 2; rh++) {
                float P = acc[0][nt][rh * 2 + cc] + bias1;
                float Q = acc[1][nt][rh * 2 + cc] + bias2;
                float R = acc[2][nt][rh * 2 + cc] + bias3;
                float sg = 1.f / (1.f + expf(-Q));
                float v = P * sg + R;
                v = v > 0.f ? v : 0.f;
                lsum += v;
                lss += v * v;
                if (r == 7) {                      // t'' = 7 row
                    int b = 2 * w + rh;
                    g_last[(size_t)(b * Nn + n) * OC + o] = v;
                }
            }
        }
    }

    // block reduce -> 2 atomics
#pragma unroll
    for (int off = 16; off > 0; off >>= 1) {
        lsum += __shfl_down_sync(0xffffffffu, lsum, off);
        lss  += __shfl_down_sync(0xffffffffu, lss,  off);
    }
    __shared__ float wsum[8], wss[8];
    if (lane == 0) { wsum[w] = lsum; wss[w] = lss; }
    __syncthreads();
    if (tid == 0) {
        float ts = 0.f, tq = 0.f;
#pragma unroll
        for (int i = 0; i < 8; i++) { ts += wsum[i]; tq += wss[i]; }
        atomicAdd(&g_sum[n], ts);
        atomicAdd(&g_sumsq[n], tq);
    }
}

// ---------------- final: BN + transpose to output ----------------
__global__ __launch_bounds__(384) void k_final(
    const float* __restrict__ gamma, const float* __restrict__ beta,
    float* __restrict__ out)
{
    int bid = blockIdx.x;
    int b = bid >> 10, n = bid & 1023;
    int c = threadIdx.x;
    float mean = g_sum[n] / STAT_CNT;
    float var = g_sumsq[n] / STAT_CNT - mean * mean;
    float inv = rsqrtf(var + 1e-5f);
    float ga = gamma[n], be = beta[n];
    float v = g_last[(size_t)bid * OC + c];
    out[(size_t)c * (Bsz * Nn) + b * Nn + n] = (v - mean) * inv * ga + be;
}

// ---------------- launch ----------------
extern "C" void kernel_launch(void* const* d_in, const int* in_sizes, int n_in,
                              void* d_out, int out_size)
{
    const float* X        = (const float*)d_in[0];
    const int*   ei       = (const int*)  d_in[1];
    const float* ew       = (const float*)d_in[2];
    const float* tc1_w1   = (const float*)d_in[3];
    const float* tc1_b1   = (const float*)d_in[4];
    const float* tc1_w2   = (const float*)d_in[5];
    const float* tc1_b2   = (const float*)d_in[6];
    const float* tc1_w3   = (const float*)d_in[7];
    const float* tc1_b3   = (const float*)d_in[8];
    const float* cheb_W   = (const float*)d_in[9];
    const float* cheb_b   = (const float*)d_in[10];
    const float* tc2_w1   = (const float*)d_in[11];
    const float* tc2_b1   = (const float*)d_in[12];
    const float* tc2_w2   = (const float*)d_in[13];
    const float* tc2_b2   = (const float*)d_in[14];
    const float* tc2_w3   = (const float*)d_in[15];
    const float* tc2_b3   = (const float*)d_in[16];
    const float* bn_gamma = (const float*)d_in[17];
    const float* bn_beta  = (const float*)d_in[18];
    float* out = (float*)d_out;

    static int smem_set = 0;
    if (!smem_set) {
        cudaFuncSetAttribute(k_conv2, cudaFuncAttributeMaxDynamicSharedMemorySize, CONV2_SMEM);
        smem_set = 1;
    }

    k_init<<<1, 1024>>>();
    k_deg<<<Ee / 256, 256>>>(ei, ew);
    k_scan<<<1, 1024>>>();
    k_scatter<<<Ee / 256, 256>>>(ei, ew);
    k_conv1<<<Bsz * Nn, 64>>>(X, tc1_w1, tc1_b1, tc1_w2, tc1_b2, tc1_w3, tc1_b3);
    k_wtrans<<<(3 * K2 * OC + 255) / 256, 256>>>(tc2_w1, tc2_w2, tc2_w3);
    k_prop<<<Nn, 256>>>(0);
    k_prop<<<Nn, 256>>>(1);
    k_chebmm<<<(Nn * BT1) / 64, 256>>>(cheb_W, cheb_b);
    k_conv2<<<dim3(6, Nn), 256, CONV2_SMEM>>>(tc2_b1, tc2_b2, tc2_b3);
    k_final<<<Bsz * Nn, 384>>>(bn_gamma, bn_beta, out);
}

// round 7
// speedup vs baseline: 2.7424x; 1.0919x over previous
#include <cuda_runtime.h>
#include <math.h>
#include <stdint.h>

// ---------------- problem constants ----------------
#define Bsz 16
#define Nn  1024
#define Cin 2
#define Tt  12
#define HIDc 64
#define T1  10          // T-2
#define T2n 8           // T-4
#define OC  384         // OUT*PRED
#define Ee  16384
#define BT1 (Bsz*T1)    // 160
#define K2  192         // HID*KT for conv2
#define STAT_CNT 49152.0f  // B*T2n*OC per-node BN count

// conv2 smem geometry
#define A_STRIDE 68                    // 64 + 4 pad -> conflict-free a-frag LDS
#define A_WORDS  (BT1 * A_STRIDE)      // 10880 u32
#define B_C_STRIDE 136                 // 128 + 8 pad -> conflict-free b-frag LDS.64
#define B_WORDS  (12 * B_C_STRIDE)     // 1632 u32 per buffer
#define CONV2_SMEM ((A_WORDS + 2 * B_WORDS) * 4)   // 56576 bytes

// ---------------- tf32 mma helpers ----------------
__device__ __forceinline__ uint32_t f2tf32(float f) {
    uint32_t u;
    asm("cvt.rna.tf32.f32 %0, %1;" : "=r"(u) : "f"(f));
    return u;
}
__device__ __forceinline__ void mma_tf32(float c[4], const uint32_t a[4],
                                         uint32_t b0, uint32_t b1) {
    asm volatile(
        "mma.sync.aligned.m16n8k8.row.col.f32.tf32.tf32.f32 "
        "{%0,%1,%2,%3},{%4,%5,%6,%7},{%8,%9},{%0,%1,%2,%3};"
        : "+f"(c[0]), "+f"(c[1]), "+f"(c[2]), "+f"(c[3])
        : "r"(a[0]), "r"(a[1]), "r"(a[2]), "r"(a[3]), "r"(b0), "r"(b1));
}

// ---------------- device scratch (static, no allocs) ----------------
__device__ float g_T0 [Nn*BT1*HIDc];   // (n, b*10+t, h)
__device__ float g_Tx1[Nn*BT1*HIDc];
__device__ float g_Tx2[Nn*BT1*HIDc];
__device__ float g_Tg [Nn*BT1*HIDc];   // tf32-rounded floats
__device__ float g_last[Bsz*Nn*OC];    // (b*Nn+n)*OC + o  (t''=7 slice, pre-BN)
__device__ uint32_t g_wt2[24*3*4*OC*2]; // conv2 weights tf32, [kc][s][c][o][half]
__device__ uint32_t g_cw [3*8*4*128];   // cheb weights tf32, [s][kc][c][n][half]
__device__ int   g_cntv[Nn];
__device__ int   g_indptr[Nn];
__device__ int   g_csr_row[Ee];
__device__ float g_csr_nrm[Ee];
__device__ float g_sum[Nn];
__device__ float g_sumsq[Nn];

// ---------------- CSR build: one block, smem atomics ----------------
__global__ __launch_bounds__(1024) void k_csr(const int* __restrict__ ei,
                                              const float* __restrict__ ew) {
    __shared__ float sdeg[Nn];
    __shared__ int   scnt[Nn];
    __shared__ float sdinv[Nn];
    __shared__ int   sptr[Nn];
    __shared__ int   scounter[Nn];
    int t = threadIdx.x;
    sdeg[t] = 0.f; scnt[t] = 0; scounter[t] = 0;
    g_sum[t] = 0.f; g_sumsq[t] = 0.f;
    __syncthreads();
#pragma unroll
    for (int q = 0; q < 16; q++) {
        int e = t + q * 1024;
        int r = ei[e], c = ei[Ee + e];
        float w = ew[e];
        if (r != c) atomicAdd(&sdeg[r], w);
        atomicAdd(&scnt[c], 1);
    }
    __syncthreads();
    float d = sdeg[t];
    sdinv[t] = (d > 0.f) ? rsqrtf(d) : 0.f;
    int cval = scnt[t];
    sptr[t] = cval;
    __syncthreads();
    for (int off = 1; off < Nn; off <<= 1) {
        int v = (t >= off) ? sptr[t - off] : 0;
        __syncthreads();
        sptr[t] += v;
        __syncthreads();
    }
    int excl = sptr[t] - cval;
    __syncthreads();
    sptr[t] = excl;
    g_cntv[t] = cval;
    g_indptr[t] = excl;
    __syncthreads();
#pragma unroll
    for (int q = 0; q < 16; q++) {
        int e = t + q * 1024;
        int r = ei[e], c = ei[Ee + e];
        float w = ew[e];
        float nm = (r == c) ? 0.f : -(sdinv[r] * w * sdinv[c]);
        int pos = sptr[c] + atomicAdd(&scounter[c], 1);
        g_csr_row[pos] = r;
        g_csr_nrm[pos] = nm;
    }
}

// ---------------- temporal conv 1 ----------------
__global__ __launch_bounds__(64) void k_conv1(
    const float* __restrict__ X,
    const float* __restrict__ w1, const float* __restrict__ b1,
    const float* __restrict__ w2, const float* __restrict__ b2,
    const float* __restrict__ w3, const float* __restrict__ b3)
{
    int bid = blockIdx.x;
    int n = bid >> 4, b = bid & 15;
    int h = threadIdx.x;
    __shared__ float sx[2][12];
    if (h < 24) {
        int c = h / 12, t = h % 12;
        sx[c][t] = X[((b * Nn + n) * 2 + c) * 12 + t];
    }
    float w1r[6], w2r[6], w3r[6];
#pragma unroll
    for (int j = 0; j < 6; j++) {
        w1r[j] = w1[h * 6 + j];
        w2r[j] = w2[h * 6 + j];
        w3r[j] = w3[h * 6 + j];
    }
    float bb1 = b1[h], bb2 = b2[h], bb3 = b3[h];
    __syncthreads();
#pragma unroll
    for (int tp = 0; tp < T1; tp++) {
        float P = bb1, Q = bb2, R = bb3;
#pragma unroll
        for (int c = 0; c < 2; c++)
#pragma unroll
            for (int k = 0; k < 3; k++) {
                float v = sx[c][tp + k];
                P += v * w1r[c * 3 + k];
                Q += v * w2r[c * 3 + k];
                R += v * w3r[c * 3 + k];
            }
        float sg = 1.f / (1.f + expf(-Q));
        float val = P * sg + R;
        val = val > 0.f ? val : 0.f;
        g_T0[(n * BT1 + b * T1 + tp) * HIDc + h] = val;
    }
}

// ---------------- conv2 weight prep: tf32 + fragment-layout swizzle ----------------
__global__ void k_wtrans(const float* __restrict__ w1,
                         const float* __restrict__ w2,
                         const float* __restrict__ w3)
{
    int idx = blockIdx.x * blockDim.x + threadIdx.x;
    if (idx >= 3 * K2 * OC) return;
    int s = idx / (K2 * OC);
    int r = idx % (K2 * OC);
    int k = r / OC, o = r % OC;
    int h = k & 63, dt = k >> 6;
    const float* w = (s == 0) ? w1 : (s == 1) ? w2 : w3;
    int kc = dt * 8 + (h >> 3);
    int kl = h & 7;
    int c = kl & 3, half = kl >> 2;
    g_wt2[(((kc * 3 + s) * 4 + c) * OC + o) * 2 + half] =
        f2tf32(w[(o * HIDc + h) * 3 + dt]);
}

// ---------------- cheb weight prep: tf32 fragment layout ----------------
// g_cw[((s*8+kc)*4 + c)*128 + n*2 + h] = tf32(chebW[s][kc*8 + h*4 + c][n])
__global__ void k_cwtrans(const float* __restrict__ chebW) {
    int idx = blockIdx.x * blockDim.x + threadIdx.x;
    if (idx >= 3 * 8 * 4 * 128) return;
    int s = idx / 4096;
    int rem = idx % 4096;
    int kc = rem / 512;
    int c = (rem / 128) % 4;
    int nj = rem % 128;
    int n = nj >> 1, h = nj & 1;
    g_cw[idx] = f2tf32(chebW[s * 4096 + (kc * 8 + h * 4 + c) * HIDc + n]);
}

// ---------------- graph propagation (gather CSR) ----------------
__global__ __launch_bounds__(256) void k_prop(int mode) {
    const float* __restrict__ z = (mode == 0) ? g_T0 : g_Tx1;
    float* __restrict__ out = (mode == 0) ? g_Tx1 : g_Tx2;
    int j = blockIdx.x;
    int tid = threadIdx.x;
    int hq = tid & 15;
    int g = tid >> 4;
    float4 acc[10];
#pragma unroll
    for (int i = 0; i < 10; i++) acc[i] = make_float4(0.f, 0.f, 0.f, 0.f);

    int start = g_indptr[j], cnt = g_cntv[j];
    __shared__ int sr[64];
    __shared__ float sn[64];
    for (int eb = 0; eb < cnt; eb += 64) {
        int m = cnt - eb; if (m > 64) m = 64;
        if (tid < m) { sr[tid] = g_csr_row[start + eb + tid]; sn[tid] = g_csr_nrm[start + eb + tid]; }
        __syncthreads();
        for (int e = 0; e < m; e++) {
            int r = sr[e];
            float nm = sn[e];
            const float4* zp = (const float4*)z + (size_t)(r * BT1 + g * 10) * 16 + hq;
#pragma unroll
            for (int i = 0; i < 10; i++) {
                float4 v = zp[(size_t)i * 16];
                acc[i].x += nm * v.x; acc[i].y += nm * v.y;
                acc[i].z += nm * v.z; acc[i].w += nm * v.w;
            }
        }
        __syncthreads();
    }
    float4* op = (float4*)out + (size_t)(j * BT1 + g * 10) * 16 + hq;
    if (mode == 0) {
#pragma unroll
        for (int i = 0; i < 10; i++) op[(size_t)i * 16] = acc[i];
    } else {
        const float4* sp = (const float4*)g_T0 + (size_t)(j * BT1 + g * 10) * 16 + hq;
#pragma unroll
        for (int i = 0; i < 10; i++) {
            float4 s0 = sp[(size_t)i * 16];
            float4 o4;
            o4.x = 2.f * acc[i].x - s0.x; o4.y = 2.f * acc[i].y - s0.y;
            o4.z = 2.f * acc[i].z - s0.z; o4.w = 2.f * acc[i].w - s0.w;
            op[(size_t)i * 16] = o4;
        }
    }
}

// ---------------- cheb combine: tf32 mma ----------------
// grid 2560: m-tile of 64 rows. 256 threads = 8 warps: warp = (nh<<2)|mw.
// acc accumulates over 3 srcs; bias+relu+tf32-round epilogue to g_Tg.
__global__ __launch_bounds__(256) void k_chebmm(const float* __restrict__ chebB)
{
    __shared__ uint32_t sA[64 * A_STRIDE];     // 4352 u32
    __shared__ uint32_t sB[32 * B_C_STRIDE];   // 4352 u32
    int m0 = blockIdx.x * 64;
    int tid = threadIdx.x;
    int lane = tid & 31, w = tid >> 5;
    int mw = w & 3, nh = w >> 2;
    int r = lane >> 2, c = lane & 3;

    float acc[4][4];
#pragma unroll
    for (int nt = 0; nt < 4; nt++)
#pragma unroll
        for (int i = 0; i < 4; i++) acc[nt][i] = 0.f;

    const float* srcs[3] = { g_T0, g_Tx1, g_Tx2 };
    for (int s = 0; s < 3; s++) {
        // ---- load A 64x64 (cvt to tf32) ----
        const float4* gA = (const float4*)(srcs[s] + (size_t)m0 * HIDc);
#pragma unroll
        for (int q = 0; q < 4; q++) {
            int i4 = tid + q * 256;            // 0..1023
            int row = i4 >> 4, h4 = (i4 & 15) * 4;
            float4 v = gA[i4];
            uint32_t* dst = &sA[row * A_STRIDE + h4];
            dst[0] = f2tf32(v.x); dst[1] = f2tf32(v.y);
            dst[2] = f2tf32(v.z); dst[3] = f2tf32(v.w);
        }
        // ---- load B (pre-swizzled tf32): 2048 uint2 ----
        const uint2* gB = (const uint2*)(g_cw + s * 4096);
#pragma unroll
        for (int q = 0; q < 8; q++) {
            int i2 = tid + q * 256;            // 0..2047
            int row = i2 >> 6, j = i2 & 63;
            *(uint2*)&sB[row * B_C_STRIDE + j * 2] = gB[i2];
        }
        __syncthreads();
#pragma unroll
        for (int kc = 0; kc < 8; kc++) {
            uint32_t a[4];
            int abase = (mw * 16 + r) * A_STRIDE + kc * 8 + c;
            a[0] = sA[abase];
            a[1] = sA[abase + 8 * A_STRIDE];
            a[2] = sA[abase + 4];
            a[3] = sA[abase + 8 * A_STRIDE + 4];
#pragma unroll
            for (int nt = 0; nt < 4; nt++) {
                uint2 bv = *(const uint2*)&sB[(kc * 4 + c) * B_C_STRIDE + (nh * 32 + nt * 8 + r) * 2];
                mma_tf32(acc[nt], a, bv.x, bv.y);
            }
        }
        __syncthreads();
    }
    // ---- epilogue: bias + relu + tf32 round ----
#pragma unroll
    for (int nt = 0; nt < 4; nt++) {
        int n0 = nh * 32 + nt * 8 + c * 2;
        float bb0 = chebB[n0], bb1 = chebB[n0 + 1];
        float v0 = acc[nt][0] + bb0; v0 = v0 > 0.f ? v0 : 0.f;
        float v1 = acc[nt][1] + bb1; v1 = v1 > 0.f ? v1 : 0.f;
        float v2 = acc[nt][2] + bb0; v2 = v2 > 0.f ? v2 : 0.f;
        float v3 = acc[nt][3] + bb1; v3 = v3 > 0.f ? v3 : 0.f;
        float2 p0, p1;
        p0.x = __uint_as_float(f2tf32(v0)); p0.y = __uint_as_float(f2tf32(v1));
        p1.x = __uint_as_float(f2tf32(v2)); p1.y = __uint_as_float(f2tf32(v3));
        *(float2*)&g_Tg[(size_t)(m0 + mw * 16 + r) * HIDc + n0] = p0;
        *(float2*)&g_Tg[(size_t)(m0 + mw * 16 + r + 8) * HIDc + n0] = p1;
    }
}

// ---------------- temporal conv 2: tf32 mma, A resident in smem ----------------
__global__ __launch_bounds__(256) void k_conv2(
    const float* __restrict__ b1, const float* __restrict__ b2, const float* __restrict__ b3)
{
    extern __shared__ uint32_t sh[];
    uint32_t* sA = sh;                 // [bt:160][h:64] stride A_STRIDE
    uint32_t* sB = sh + A_WORDS;       // 2 buffers of B_WORDS
    int n = blockIdx.y;
    int o0 = blockIdx.x * 64;
    int tid = threadIdx.x;
    int lane = tid & 31, w = tid >> 5;
    int r = lane >> 2, c = lane & 3;

    const uint4* gT = (const uint4*)(g_Tg + (size_t)n * (BT1 * HIDc));
#pragma unroll
    for (int q = 0; q < 10; q++) {
        int idx4 = tid + q * 256;
        int bt = idx4 >> 4;
        int h4 = (idx4 & 15) * 4;
        *(uint4*)&sA[bt * A_STRIDE + h4] = gT[idx4];
    }
    const uint2* gW = (const uint2*)g_wt2;
#pragma unroll
    for (int q = 0; q < 3; q++) {
        int idx2 = tid + q * 256;
        int sc = idx2 >> 6, j2 = idx2 & 63;
        *(uint2*)&sB[sc * B_C_STRIDE + j2 * 2] = gW[sc * 384 + o0 + j2];
    }
    __syncthreads();

    float acc[3][8][4];
#pragma unroll
    for (int s = 0; s < 3; s++)
#pragma unroll
        for (int nt = 0; nt < 8; nt++)
#pragma unroll
            for (int i = 0; i < 4; i++) acc[s][nt][i] = 0.f;

    for (int kc = 0; kc < 24; kc++) {
        int cur = (kc & 1) ? B_WORDS : 0;
        if (kc < 23) {
            int nxt = B_WORDS - cur;
            int gbase = (kc + 1) * 4608;
#pragma unroll
            for (int q = 0; q < 3; q++) {
                int idx2 = tid + q * 256;
                int sc = idx2 >> 6, j2 = idx2 & 63;
                *(uint2*)&sB[nxt + sc * B_C_STRIDE + j2 * 2] = gW[gbase + sc * 384 + o0 + j2];
            }
        }
        int dt = kc >> 3;
        int hbase = (kc & 7) << 3;
        int bt0 = 20 * w + r + dt;
        uint32_t a[4];
        a[0] = sA[bt0 * A_STRIDE + hbase + c];
        a[1] = sA[(bt0 + 10) * A_STRIDE + hbase + c];
        a[2] = sA[bt0 * A_STRIDE + hbase + c + 4];
        a[3] = sA[(bt0 + 10) * A_STRIDE + hbase + c + 4];
#pragma unroll
        for (int s = 0; s < 3; s++)
#pragma unroll
            for (int nt = 0; nt < 8; nt++) {
                uint2 bv = *(const uint2*)&sB[cur + (s * 4 + c) * B_C_STRIDE + (nt * 8 + r) * 2];
                mma_tf32(acc[s][nt], a, bv.x, bv.y);
            }
        __syncthreads();
    }

    int col2 = c * 2;
    float lsum = 0.f, lss = 0.f;
#pragma unroll
    for (int nt = 0; nt < 8; nt++) {
#pragma unroll
        for (int cc = 0; cc < 2; cc++) {
            int o = o0 + nt * 8 + col2 + cc;
            float bias1 = b1[o], bias2 = b2[o], bias3 = b3[o];
#pragma unroll
            for (int rh = 0; rh < 2; rh++) {
                float P = acc[0][nt][rh * 2 + cc] + bias1;
                float Q = acc[1][nt][rh * 2 + cc] + bias2;
                float R = acc[2][nt][rh * 2 + cc] + bias3;
                float sg = 1.f / (1.f + expf(-Q));
                float v = P * sg + R;
                v = v > 0.f ? v : 0.f;
                lsum += v;
                lss += v * v;
                if (r == 7) {
                    int b = 2 * w + rh;
                    g_last[(size_t)(b * Nn + n) * OC + o] = v;
                }
            }
        }
    }

#pragma unroll
    for (int off = 16; off > 0; off >>= 1) {
        lsum += __shfl_down_sync(0xffffffffu, lsum, off);
        lss  += __shfl_down_sync(0xffffffffu, lss,  off);
    }
    __shared__ float wsum[8], wss[8];
    if (lane == 0) { wsum[w] = lsum; wss[w] = lss; }
    __syncthreads();
    if (tid == 0) {
        float ts = 0.f, tq = 0.f;
#pragma unroll
        for (int i = 0; i < 8; i++) { ts += wsum[i]; tq += wss[i]; }
        atomicAdd(&g_sum[n], ts);
        atomicAdd(&g_sumsq[n], tq);
    }
}

// ---------------- final: BN + transpose to output ----------------
__global__ __launch_bounds__(384) void k_final(
    const float* __restrict__ gamma, const float* __restrict__ beta,
    float* __restrict__ out)
{
    int bid = blockIdx.x;
    int b = bid >> 10, n = bid & 1023;
    int c = threadIdx.x;
    float mean = g_sum[n] / STAT_CNT;
    float var = g_sumsq[n] / STAT_CNT - mean * mean;
    float inv = rsqrtf(var + 1e-5f);
    float ga = gamma[n], be = beta[n];
    float v = g_last[(size_t)bid * OC + c];
    out[(size_t)c * (Bsz * Nn) + b * Nn + n] = (v - mean) * inv * ga + be;
}

// ---------------- launch ----------------
extern "C" void kernel_launch(void* const* d_in, const int* in_sizes, int n_in,
                              void* d_out, int out_size)
{
    const float* X        = (const float*)d_in[0];
    const int*   ei       = (const int*)  d_in[1];
    const float* ew       = (const float*)d_in[2];
    const float* tc1_w1   = (const float*)d_in[3];
    const float* tc1_b1   = (const float*)d_in[4];
    const float* tc1_w2   = (const float*)d_in[5];
    const float* tc1_b2   = (const float*)d_in[6];
    const float* tc1_w3   = (const float*)d_in[7];
    const float* tc1_b3   = (const float*)d_in[8];
    const float* cheb_W   = (const float*)d_in[9];
    const float* cheb_b   = (const float*)d_in[10];
    const float* tc2_w1   = (const float*)d_in[11];
    const float* tc2_b1   = (const float*)d_in[12];
    const float* tc2_w2   = (const float*)d_in[13];
    const float* tc2_b2   = (const float*)d_in[14];
    const float* tc2_w3   = (const float*)d_in[15];
    const float* tc2_b3   = (const float*)d_in[16];
    const float* bn_gamma = (const float*)d_in[17];
    const float* bn_beta  = (const float*)d_in[18];
    float* out = (float*)d_out;

    static int smem_set = 0;
    if (!smem_set) {
        cudaFuncSetAttribute(k_conv2, cudaFuncAttributeMaxDynamicSharedMemorySize, CONV2_SMEM);
        smem_set = 1;
    }

    k_csr<<<1, 1024>>>(ei, ew);
    k_conv1<<<Bsz * Nn, 64>>>(X, tc1_w1, tc1_b1, tc1_w2, tc1_b2, tc1_w3, tc1_b3);
    k_wtrans<<<(3 * K2 * OC + 255) / 256, 256>>>(tc2_w1, tc2_w2, tc2_w3);
    k_cwtrans<<<48, 256>>>(cheb_W);
    k_prop<<<Nn, 256>>>(0);
    k_prop<<<Nn, 256>>>(1);
    k_chebmm<<<(Nn * BT1) / 64, 256>>>(cheb_b);
    k_conv2<<<dim3(6, Nn), 256, CONV2_SMEM>>>(tc2_b1, tc2_b2, tc2_b3);
    k_final<<<Bsz * Nn, 384>>>(bn_gamma, bn_beta, out);
}